// round 10
// baseline (speedup 1.0000x reference)
#include <cuda_runtime.h>
#include <cuda_fp16.h>
#include <cstdint>

#define N_FEAT 256
#define ROWS 128                       // M rows per CTA

// B in fragment order, global, uint4-packed pairs of interleaved subs:
//   G[jt(4)][kb(16)][jh(2)][pi(2)][lane(32)] -> uint4
//   pi=0: .x/.y = acc s=0 (sub=jh)   k-lo/k-hi,  .z/.w = acc s=1 (sub=jh+2)
//   pi=1: .x/.y = acc s=2 (sub=jh+4),            .z/.w = acc s=3 (sub=jh+6)
// sub s covers cols j = jt*64 + sub*8 + (lane>>2),
// k-lo = half2(L[k0][j],L[k0+1][j]), k-hi = +8, k0 = kb*16 + (lane&3)*2.
// L[k][j] = W[k][j] if k > j else 0 (strict lower; validated R1).
__device__ __align__(16) uint4 g_Bf[4 * 16 * 2 * 2 * 32];

// ---- smem layout (bytes) ----
#define OFF_AFRAG 0                    // 8 rg16 x 16 kb x 32 lanes x uint4 = 64KB
#define OFF_WL    65536                // 256 floats
#define OFF_RS    66560                // 128 floats rowsum
#define SMEM_TOTAL 67072

// ---------------------------------------------------------------------------
// Prep: W[k][j] = sum_m v[k,f(j),m] * v[j,f(k),m]  -> fp16 fragments
// ---------------------------------------------------------------------------
__global__ void ffm_prep(const float* __restrict__ v, const int* __restrict__ fidx) {
    int idx = blockIdx.x * blockDim.x + threadIdx.x;   // 0 .. 16383
    if (idx >= 4 * 16 * 8 * 32) return;
    int lane = idx & 31;
    int sub  = (idx >> 5) & 7;
    int kb   = (idx >> 8) & 15;
    int jt   = idx >> 12;
    int g  = lane >> 2, tg = lane & 3;
    int j  = jt * 64 + sub * 8 + g;
    int k0 = kb * 16 + tg * 2;
    int fj = fidx[j];
    const float* vjr = v + (j * 32) * 8;

    float lv[4];
    int kk[4] = {k0, k0 + 1, k0 + 8, k0 + 9};
#pragma unroll
    for (int q = 0; q < 4; ++q) {
        int k = kk[q];
        float s = 0.f;
        if (k > j) {
            int fk = fidx[k];
            const float* a = v + (k * 32 + fj) * 8;
            const float* b = vjr + fk * 8;
#pragma unroll
            for (int m = 0; m < 8; ++m) s += a[m] * b[m];
        }
        lv[q] = s;
    }
    __half2 w0 = __floats2half2_rn(lv[0], lv[1]);
    __half2 w1 = __floats2half2_rn(lv[2], lv[3]);

    int jh   = sub & 1;
    int sl   = sub >> 1;          // acc index s
    int pi   = sl >> 1;
    int half = sl & 1;
    int U = (((jt * 16 + kb) * 2 + jh) * 2 + pi) * 32 + lane;
    uint32_t* g32 = reinterpret_cast<uint32_t*>(g_Bf);
    g32[U * 4 + half * 2]     = *reinterpret_cast<uint32_t*>(&w0);
    g32[U * 4 + half * 2 + 1] = *reinterpret_cast<uint32_t*>(&w1);
}

// ---------------------------------------------------------------------------
__device__ __forceinline__ void mma_f16(float c[4], const uint4& a, uint32_t b0, uint32_t b1) {
    asm volatile(
        "mma.sync.aligned.m16n8k16.row.col.f32.f16.f16.f32 "
        "{%0,%1,%2,%3}, {%4,%5,%6,%7}, {%8,%9}, {%0,%1,%2,%3};\n"
        : "+f"(c[0]), "+f"(c[1]), "+f"(c[2]), "+f"(c[3])
        : "r"(a.x), "r"(a.y), "r"(a.z), "r"(a.w), "r"(b0), "r"(b1));
}

// Main: Z = X * L (fp16, coarse triangular skip), fused epilogue.
// 256 threads = 8 warps: warp = rgpair(0..3) x jhalf(0..1).
// Each warp: M = 32 rows (row-groups rgpair*2, rgpair*2+1) x N = 32 cols
// (interleaved subs jhalf, jhalf+2, jhalf+4, jhalf+6). 8 acc chains; B reused 2x.
__global__ __launch_bounds__(256, 2) void ffm_main(
    const float* __restrict__ x, const float* __restrict__ wl,
    const float* __restrict__ bl, float* __restrict__ out, int Bn) {
    extern __shared__ char smem[];
    uint4*  afrag  = reinterpret_cast<uint4*>(smem + OFF_AFRAG);
    float*  wls    = reinterpret_cast<float*>(smem + OFF_WL);
    float*  rowsum = reinterpret_cast<float*>(smem + OFF_RS);

    const int tid  = threadIdx.x;
    const int row0 = blockIdx.x * ROWS;

    if (tid < 128) rowsum[tid] = 0.f;
    wls[tid] = wl[tid];     // 256 threads, 256 entries

    // ---- stage A fragments: x fp32 -> fp16, mma a-fragment order ----
    for (int it = tid; it < 4096; it += 256) {
        int ln = it & 31;
        int kb = (it >> 5) & 15;
        int rg = it >> 9;
        int g = ln >> 2, tg = ln & 3;
        int r0 = rg * 16 + g, r1 = r0 + 8;
        int c0 = kb * 16 + tg * 2;
        int gr0 = row0 + r0, gr1 = row0 + r1;
        float2 z2 = make_float2(0.f, 0.f);
        float2 v00 = (gr0 < Bn) ? *reinterpret_cast<const float2*>(x + (size_t)gr0 * N_FEAT + c0)     : z2;
        float2 v01 = (gr0 < Bn) ? *reinterpret_cast<const float2*>(x + (size_t)gr0 * N_FEAT + c0 + 8) : z2;
        float2 v10 = (gr1 < Bn) ? *reinterpret_cast<const float2*>(x + (size_t)gr1 * N_FEAT + c0)     : z2;
        float2 v11 = (gr1 < Bn) ? *reinterpret_cast<const float2*>(x + (size_t)gr1 * N_FEAT + c0 + 8) : z2;
        __half2 h00 = __floats2half2_rn(v00.x, v00.y);
        __half2 h10 = __floats2half2_rn(v10.x, v10.y);
        __half2 h01 = __floats2half2_rn(v01.x, v01.y);
        __half2 h11 = __floats2half2_rn(v11.x, v11.y);
        uint4 o;
        o.x = *reinterpret_cast<uint32_t*>(&h00);
        o.y = *reinterpret_cast<uint32_t*>(&h10);
        o.z = *reinterpret_cast<uint32_t*>(&h01);
        o.w = *reinterpret_cast<uint32_t*>(&h11);
        afrag[(rg * 16 + kb) * 32 + ln] = o;
    }
    __syncthreads();

    const int wid = tid >> 5, lane = tid & 31;
    const int rgpair = wid >> 1, jhalf = wid & 1;
    const int rgA = rgpair * 2;            // first 16-row group; second is rgA+1
    const int g = lane >> 2, tg = lane & 3;

    float partial0 = 0.f, partial1 = 0.f, partial2 = 0.f, partial3 = 0.f;

    for (int jt = 0; jt < 4; ++jt) {
        float acc[8][4];
#pragma unroll
        for (int s = 0; s < 8; ++s)
#pragma unroll
            for (int q = 0; q < 4; ++q) acc[s][q] = 0.f;

        const int nk = 16 - 4 * jt;        // coarse skip: kb = 4jt .. 15
        const uint4* ap0 = &afrag[(rgA * 16 + 4 * jt) * 32 + lane];
        const uint4* ap1 = ap0 + 16 * 32;
        const uint4* bp  = &g_Bf[(((jt * 16 + 4 * jt) * 2 + jhalf) * 2) * 32 + lane];

        uint4 aL = ap0[0], aH = ap1[0];
        uint4 p0 = bp[0],  p1 = bp[32];

        for (int k = 0; k < nk; ++k) {
            uint4 aLn, aHn, p0n, p1n;
            if (k + 1 < nk) {
                aLn = ap0[(k + 1) * 32];
                aHn = ap1[(k + 1) * 32];
                p0n = bp[(k + 1) * 128];
                p1n = bp[(k + 1) * 128 + 32];
            }
            mma_f16(acc[0], aL, p0.x, p0.y);
            mma_f16(acc[1], aL, p0.z, p0.w);
            mma_f16(acc[2], aL, p1.x, p1.y);
            mma_f16(acc[3], aL, p1.z, p1.w);
            mma_f16(acc[4], aH, p0.x, p0.y);
            mma_f16(acc[5], aH, p0.z, p0.w);
            mma_f16(acc[6], aH, p1.x, p1.y);
            mma_f16(acc[7], aH, p1.z, p1.w);
            aL = aLn; aH = aHn; p0 = p0n; p1 = p1n;
        }

        // ---- fused epilogue: partial += (Z + w) .* x over this warp's tile ----
        // acc[s]   (s=0..3): rows g / g+8      of rgA,   sub = jhalf + 2s
        // acc[4+s]          : rows g+16 / g+24 (rgA+1),  same subs
        // x cols for sub live in afrag at kb' = 4jt + s; jhalf picks lo/hi 8-col half.
#pragma unroll
        for (int s = 0; s < 4; ++s) {
            uint4 av1 = afrag[(rgA * 16 + 4 * jt + s) * 32 + lane];
            uint4 av2 = afrag[((rgA + 1) * 16 + 4 * jt + s) * 32 + lane];
            int sub = jhalf + 2 * s;
            int jb = jt * 64 + sub * 8 + tg * 2;
            float w0 = wls[jb], w1 = wls[jb + 1];
            uint32_t u0 = jhalf ? av1.z : av1.x;   // row g
            uint32_t u1 = jhalf ? av1.w : av1.y;   // row g+8
            uint32_t u2 = jhalf ? av2.z : av2.x;   // row g+16
            uint32_t u3 = jhalf ? av2.w : av2.y;   // row g+24
            float2 x0 = __half22float2(*reinterpret_cast<__half2*>(&u0));
            float2 x1 = __half22float2(*reinterpret_cast<__half2*>(&u1));
            float2 x2 = __half22float2(*reinterpret_cast<__half2*>(&u2));
            float2 x3 = __half22float2(*reinterpret_cast<__half2*>(&u3));
            partial0 += (acc[s][0]     + w0) * x0.x + (acc[s][1]     + w1) * x0.y;
            partial1 += (acc[s][2]     + w0) * x1.x + (acc[s][3]     + w1) * x1.y;
            partial2 += (acc[4 + s][0] + w0) * x2.x + (acc[4 + s][1] + w1) * x2.y;
            partial3 += (acc[4 + s][2] + w0) * x3.x + (acc[4 + s][3] + w1) * x3.y;
        }
    }

    // reduce over the 4 lanes (tg) sharing each row
    partial0 += __shfl_xor_sync(0xffffffffu, partial0, 1);
    partial0 += __shfl_xor_sync(0xffffffffu, partial0, 2);
    partial1 += __shfl_xor_sync(0xffffffffu, partial1, 1);
    partial1 += __shfl_xor_sync(0xffffffffu, partial1, 2);
    partial2 += __shfl_xor_sync(0xffffffffu, partial2, 1);
    partial2 += __shfl_xor_sync(0xffffffffu, partial2, 2);
    partial3 += __shfl_xor_sync(0xffffffffu, partial3, 1);
    partial3 += __shfl_xor_sync(0xffffffffu, partial3, 2);

    if (tg == 0) {
        int rb = rgpair * 32 + g;
        atomicAdd(&rowsum[rb],      partial0);
        atomicAdd(&rowsum[rb + 8],  partial1);
        atomicAdd(&rowsum[rb + 16], partial2);
        atomicAdd(&rowsum[rb + 24], partial3);
    }
    __syncthreads();

    if (tid < 128) {
        int gr = row0 + tid;
        if (gr < Bn) out[gr] = rowsum[tid] + bl[0];
    }
}

// ---------------------------------------------------------------------------
extern "C" void kernel_launch(void* const* d_in, const int* in_sizes, int n_in,
                              void* d_out, int out_size) {
    const float* x    = (const float*)d_in[0];
    const float* wlin = (const float*)d_in[1];
    const float* blin = (const float*)d_in[2];
    const float* v    = (const float*)d_in[3];
    const int*   fidx = (const int*)d_in[4];
    float* out = (float*)d_out;

    int Bn = in_sizes[0] / N_FEAT;

    ffm_prep<<<32, 512>>>(v, fidx);

    cudaFuncSetAttribute(ffm_main, cudaFuncAttributeMaxDynamicSharedMemorySize, SMEM_TOTAL);
    int grid = (Bn + ROWS - 1) / ROWS;
    ffm_main<<<grid, 256, SMEM_TOTAL>>>(x, wlin, blin, out, Bn);
}

// round 11
// speedup vs baseline: 1.3205x; 1.3205x over previous
#include <cuda_runtime.h>
#include <cuda_fp16.h>
#include <cstdint>

#define N_FEAT 256
#define ROWS 112                       // M rows per CTA (7 row-groups of 16)
#define NRG  7
#define NTHR 448                       // 14 warps = 7 rg x 2 jhalf

// B in fragment order, global: [jt(4)][kb(16)][sub(8)][lane(32)] -> uint2
// word0 = half2( L[k0][j], L[k0+1][j] ),  word1 = half2( L[k0+8][j], L[k0+9][j] )
// with j = jt*64 + sub*8 + (lane>>2), k0 = kb*16 + (lane&3)*2
// L[k][j] = W[k][j] if k > j else 0  (strict lower; validated R1).
__device__ __align__(16) uint2 g_Bf[4 * 16 * 8 * 32];

// ---- smem layout (bytes) ----
#define OFF_AFRAG 0                    // 7 rg x 16 kb x 32 lanes x uint4 = 57344 B
#define OFF_WL    57344                // 256 floats
#define OFF_RS    58368                // 112 floats rowsum (padded)
#define SMEM_TOTAL 58880

// ---------------------------------------------------------------------------
// Prep: W[k][j] = sum_m v[k,f(j),m] * v[j,f(k),m]  -> fp16 fragments
// 128 blocks x 128 threads: all SMs busy.
// ---------------------------------------------------------------------------
__global__ void ffm_prep(const float* __restrict__ v, const int* __restrict__ fidx) {
    int idx = blockIdx.x * blockDim.x + threadIdx.x;   // 0 .. 16383
    if (idx >= 4 * 16 * 8 * 32) return;
    int lane = idx & 31;
    int sub  = (idx >> 5) & 7;
    int kb   = (idx >> 8) & 15;
    int jt   = idx >> 12;
    int g  = lane >> 2, tg = lane & 3;
    int j  = jt * 64 + sub * 8 + g;
    int k0 = kb * 16 + tg * 2;
    int fj = fidx[j];
    const float* vjr = v + (j * 32) * 8;   // v[j, :, :]

    float lv[4];
    int kk[4] = {k0, k0 + 1, k0 + 8, k0 + 9};
#pragma unroll
    for (int q = 0; q < 4; ++q) {
        int k = kk[q];
        float s = 0.f;
        if (k > j) {
            int fk = fidx[k];
            const float* a = v + (k * 32 + fj) * 8;
            const float* b = vjr + fk * 8;
#pragma unroll
            for (int m = 0; m < 8; ++m) s += a[m] * b[m];
        }
        lv[q] = s;
    }
    __half2 w0 = __floats2half2_rn(lv[0], lv[1]);
    __half2 w1 = __floats2half2_rn(lv[2], lv[3]);
    uint2 o;
    o.x = *reinterpret_cast<uint32_t*>(&w0);
    o.y = *reinterpret_cast<uint32_t*>(&w1);
    g_Bf[idx] = o;
}

// ---------------------------------------------------------------------------
__device__ __forceinline__ void mma_f16(float c[4], const uint32_t a[4], const uint32_t b[2]) {
    asm volatile(
        "mma.sync.aligned.m16n8k16.row.col.f32.f16.f16.f32 "
        "{%0,%1,%2,%3}, {%4,%5,%6,%7}, {%8,%9}, {%0,%1,%2,%3};\n"
        : "+f"(c[0]), "+f"(c[1]), "+f"(c[2]), "+f"(c[3])
        : "r"(a[0]), "r"(a[1]), "r"(a[2]), "r"(a[3]), "r"(b[0]), "r"(b[1]));
}

// Main: Z = X * L (fp16 single-term, coarse triangular skip), fused epilogue
//       out[b] = sum_j x[b,j] * (w[j] + Z[b,j]) + b_lin
// 448 threads = 14 warps: warp = rg(0..6) x jhalf(0..1). 2 CTAs/SM.
__global__ __launch_bounds__(NTHR, 2) void ffm_main(
    const float* __restrict__ x, const float* __restrict__ wl,
    const float* __restrict__ bl, float* __restrict__ out, int Bn) {
    extern __shared__ char smem[];
    uint4*  afrag  = reinterpret_cast<uint4*>(smem + OFF_AFRAG);
    float*  wls    = reinterpret_cast<float*>(smem + OFF_WL);
    float*  rowsum = reinterpret_cast<float*>(smem + OFF_RS);

    const int tid  = threadIdx.x;
    const int row0 = blockIdx.x * ROWS;

    if (tid < 256) wls[tid] = wl[tid];
    if (tid < ROWS) rowsum[tid] = 0.f;

    // ---- stage A fragments: x fp32 -> fp16, mma a-fragment order ----
    // afrag[(rg*16+kb)*32 + lane] = {h2(r0,klo), h2(r1,klo), h2(r0,khi), h2(r1,khi)}
    for (int it = tid; it < NRG * 16 * 32; it += NTHR) {
        int ln = it & 31;
        int kb = (it >> 5) & 15;
        int rg = it >> 9;
        int g = ln >> 2, tg = ln & 3;
        int r0 = rg * 16 + g, r1 = r0 + 8;
        int c0 = kb * 16 + tg * 2;
        int gr0 = row0 + r0, gr1 = row0 + r1;
        float2 z2 = make_float2(0.f, 0.f);
        float2 v00 = (gr0 < Bn) ? *reinterpret_cast<const float2*>(x + (size_t)gr0 * N_FEAT + c0)     : z2;
        float2 v01 = (gr0 < Bn) ? *reinterpret_cast<const float2*>(x + (size_t)gr0 * N_FEAT + c0 + 8) : z2;
        float2 v10 = (gr1 < Bn) ? *reinterpret_cast<const float2*>(x + (size_t)gr1 * N_FEAT + c0)     : z2;
        float2 v11 = (gr1 < Bn) ? *reinterpret_cast<const float2*>(x + (size_t)gr1 * N_FEAT + c0 + 8) : z2;
        __half2 h00 = __floats2half2_rn(v00.x, v00.y);
        __half2 h10 = __floats2half2_rn(v10.x, v10.y);
        __half2 h01 = __floats2half2_rn(v01.x, v01.y);
        __half2 h11 = __floats2half2_rn(v11.x, v11.y);
        uint4 o;
        o.x = *reinterpret_cast<uint32_t*>(&h00);
        o.y = *reinterpret_cast<uint32_t*>(&h10);
        o.z = *reinterpret_cast<uint32_t*>(&h01);
        o.w = *reinterpret_cast<uint32_t*>(&h11);
        afrag[(rg * 16 + kb) * 32 + ln] = o;
    }
    __syncthreads();

    const int wid = tid >> 5, lane = tid & 31;
    const int rg = wid >> 1, jhalf = wid & 1;
    const int g = lane >> 2, tg = lane & 3;

    float partial0 = 0.f, partial1 = 0.f;

    for (int jt = 0; jt < 4; ++jt) {
        const int kb0 = jt * 4;

        float acc[4][4];
#pragma unroll
        for (int s = 0; s < 4; ++s)
#pragma unroll
            for (int q = 0; q < 4; ++q) acc[s][q] = 0.f;

        const uint4* ap = &afrag[(rg * 16 + kb0) * 32 + lane];
        const uint2* bp = &g_Bf[((jt * 16 + kb0) * 8 + jhalf * 4) * 32 + lane];

        // prefetch first
        uint4 a_cur = *ap;
        uint2 b_cur[4];
#pragma unroll
        for (int s = 0; s < 4; ++s) b_cur[s] = bp[s * 32];

        for (int kb = kb0; kb < 16; ++kb) {
            uint4 a_nxt;
            uint2 b_nxt[4];
            if (kb + 1 < 16) {
                a_nxt = ap[32];
#pragma unroll
                for (int s = 0; s < 4; ++s) b_nxt[s] = bp[256 + s * 32];
            }
            uint32_t a[4] = {a_cur.x, a_cur.y, a_cur.z, a_cur.w};
#pragma unroll
            for (int s = 0; s < 4; ++s) {
                uint32_t b[2] = {b_cur[s].x, b_cur[s].y};
                mma_f16(acc[s], a, b);
            }
            a_cur = a_nxt;
#pragma unroll
            for (int s = 0; s < 4; ++s) b_cur[s] = b_nxt[s];
            ap += 32;
            bp += 256;
        }

        // ---- fused epilogue: partial += (Z + w) .* x over this warp's 32 cols ----
        // acc indexed by LOCAL sub sl; global sub se used only for column numbering.
#pragma unroll
        for (int spair = 0; spair < 2; ++spair) {
            int kbp = jt * 4 + jhalf * 2 + spair;
            uint4 av = afrag[(rg * 16 + kbp) * 32 + lane];
            int sl = spair * 2;
            int se = jhalf * 4 + sl;
            int jbase = jt * 64 + se * 8 + tg * 2;
            float we0 = wls[jbase],     we1 = wls[jbase + 1];
            float wo0 = wls[jbase + 8], wo1 = wls[jbase + 9];
            float2 xe0 = __half22float2(*reinterpret_cast<__half2*>(&av.x));  // row g, even sub
            float2 xe1 = __half22float2(*reinterpret_cast<__half2*>(&av.y));  // row g+8
            float2 xo0 = __half22float2(*reinterpret_cast<__half2*>(&av.z));  // row g, odd sub
            float2 xo1 = __half22float2(*reinterpret_cast<__half2*>(&av.w));  // row g+8
            partial0 += (acc[sl][0] + we0) * xe0.x + (acc[sl][1] + we1) * xe0.y;
            partial1 += (acc[sl][2] + we0) * xe1.x + (acc[sl][3] + we1) * xe1.y;
            partial0 += (acc[sl + 1][0] + wo0) * xo0.x + (acc[sl + 1][1] + wo1) * xo0.y;
            partial1 += (acc[sl + 1][2] + wo0) * xo1.x + (acc[sl + 1][3] + wo1) * xo1.y;
        }
    }

    // reduce over the 4 lanes (tg) sharing each row
    partial0 += __shfl_xor_sync(0xffffffffu, partial0, 1);
    partial0 += __shfl_xor_sync(0xffffffffu, partial0, 2);
    partial1 += __shfl_xor_sync(0xffffffffu, partial1, 1);
    partial1 += __shfl_xor_sync(0xffffffffu, partial1, 2);

    if (tg == 0) {
        atomicAdd(&rowsum[rg * 16 + g],     partial0);
        atomicAdd(&rowsum[rg * 16 + g + 8], partial1);
    }
    __syncthreads();

    if (tid < ROWS) {
        int gr = row0 + tid;
        if (gr < Bn) out[gr] = rowsum[tid] + bl[0];
    }
}

// ---------------------------------------------------------------------------
extern "C" void kernel_launch(void* const* d_in, const int* in_sizes, int n_in,
                              void* d_out, int out_size) {
    const float* x    = (const float*)d_in[0];
    const float* wlin = (const float*)d_in[1];
    const float* blin = (const float*)d_in[2];
    const float* v    = (const float*)d_in[3];
    const int*   fidx = (const int*)d_in[4];
    float* out = (float*)d_out;

    int Bn = in_sizes[0] / N_FEAT;

    ffm_prep<<<128, 128>>>(v, fidx);

    cudaFuncSetAttribute(ffm_main, cudaFuncAttributeMaxDynamicSharedMemorySize, SMEM_TOTAL);
    int grid = (Bn + ROWS - 1) / ROWS;
    ffm_main<<<grid, NTHR, SMEM_TOTAL>>>(x, wlin, blin, out, Bn);
}

// round 12
// speedup vs baseline: 1.3365x; 1.0121x over previous
#include <cuda_runtime.h>
#include <cuda_fp16.h>
#include <cstdint>

#define N_FEAT 256
#define ROWS 112                       // M rows per CTA (7 row-groups of 16)
#define NRG  7
#define NTHR 448                       // 14 warps = 7 rg x 2 jhalf

// B in fragment order, global, uint4-packed (2 subs per vector):
//   G[jt(4)][kb(16)][jh(2)][pi(2)][lane(32)] -> uint4
//   .x/.y = sub (jh*4 + 2*pi)     k-lo pair / k-hi pair   (acc s = 2*pi)
//   .z/.w = sub (jh*4 + 2*pi + 1)                          (acc s = 2*pi+1)
// sub s covers cols j = jt*64 + sub*8 + (lane>>2),
// k-lo = half2(L[k0][j],L[k0+1][j]), k-hi = +8, k0 = kb*16 + (lane&3)*2.
// L[k][j] = W[k][j] if k > j else 0  (strict lower; validated R1).
__device__ __align__(16) uint4 g_Bf[4 * 16 * 2 * 2 * 32];

// ---- smem layout (bytes) ----
#define OFF_AFRAG 0                    // 7 rg x 16 kb x 32 lanes x uint4 = 57344 B
#define OFF_WL    57344                // 256 floats
#define OFF_RS    58368                // 112 floats rowsum (padded)
#define SMEM_TOTAL 58880

// ---------------------------------------------------------------------------
// Prep: W[k][j] = sum_m v[k,f(j),m] * v[j,f(k),m]  -> fp16 fragments
// 128 blocks x 128 threads: all SMs busy.
// ---------------------------------------------------------------------------
__global__ void ffm_prep(const float* __restrict__ v, const int* __restrict__ fidx) {
    int idx = blockIdx.x * blockDim.x + threadIdx.x;   // 0 .. 16383
    if (idx >= 4 * 16 * 8 * 32) return;
    int lane = idx & 31;
    int sub  = (idx >> 5) & 7;
    int kb   = (idx >> 8) & 15;
    int jt   = idx >> 12;
    int g  = lane >> 2, tg = lane & 3;
    int j  = jt * 64 + sub * 8 + g;
    int k0 = kb * 16 + tg * 2;
    int fj = fidx[j];
    const float* vjr = v + (j * 32) * 8;   // v[j, :, :]

    float lv[4];
    int kk[4] = {k0, k0 + 1, k0 + 8, k0 + 9};
#pragma unroll
    for (int q = 0; q < 4; ++q) {
        int k = kk[q];
        float s = 0.f;
        if (k > j) {
            int fk = fidx[k];
            const float* a = v + (k * 32 + fj) * 8;
            const float* b = vjr + fk * 8;
#pragma unroll
            for (int m = 0; m < 8; ++m) s += a[m] * b[m];
        }
        lv[q] = s;
    }
    __half2 w0 = __floats2half2_rn(lv[0], lv[1]);
    __half2 w1 = __floats2half2_rn(lv[2], lv[3]);

    // packed destination: contiguous subs within jh, 2 subs per uint4
    int jh   = sub >> 2;          // jhalf owning this sub
    int sl   = sub & 3;           // local acc index s
    int pi   = sl >> 1;           // which uint4 of the pair
    int half = sl & 1;            // 0 -> .x/.y, 1 -> .z/.w
    int U = (((jt * 16 + kb) * 2 + jh) * 2 + pi) * 32 + lane;
    uint32_t* g32 = reinterpret_cast<uint32_t*>(g_Bf);
    g32[U * 4 + half * 2]     = *reinterpret_cast<uint32_t*>(&w0);
    g32[U * 4 + half * 2 + 1] = *reinterpret_cast<uint32_t*>(&w1);
}

// ---------------------------------------------------------------------------
__device__ __forceinline__ void mma_f16(float c[4], const uint32_t a[4], uint32_t b0, uint32_t b1) {
    asm volatile(
        "mma.sync.aligned.m16n8k16.row.col.f32.f16.f16.f32 "
        "{%0,%1,%2,%3}, {%4,%5,%6,%7}, {%8,%9}, {%0,%1,%2,%3};\n"
        : "+f"(c[0]), "+f"(c[1]), "+f"(c[2]), "+f"(c[3])
        : "r"(a[0]), "r"(a[1]), "r"(a[2]), "r"(a[3]), "r"(b0), "r"(b1));
}

// Main: Z = X * L (fp16 single-term, coarse triangular skip), fused epilogue
//       out[b] = sum_j x[b,j] * (w[j] + Z[b,j]) + b_lin
// 448 threads = 14 warps: warp = rg(0..6) x jhalf(0..1). 2 CTAs/SM.
__global__ __launch_bounds__(NTHR, 2) void ffm_main(
    const float* __restrict__ x, const float* __restrict__ wl,
    const float* __restrict__ bl, float* __restrict__ out, int Bn) {
    extern __shared__ char smem[];
    uint4*  afrag  = reinterpret_cast<uint4*>(smem + OFF_AFRAG);
    float*  wls    = reinterpret_cast<float*>(smem + OFF_WL);
    float*  rowsum = reinterpret_cast<float*>(smem + OFF_RS);

    const int tid  = threadIdx.x;
    const int row0 = blockIdx.x * ROWS;

    if (tid < 256) wls[tid] = wl[tid];
    if (tid < ROWS) rowsum[tid] = 0.f;

    // ---- stage A fragments: x fp32 -> fp16, mma a-fragment order ----
    // afrag[(rg*16+kb)*32 + lane] = {h2(r0,klo), h2(r1,klo), h2(r0,khi), h2(r1,khi)}
    for (int it = tid; it < NRG * 16 * 32; it += NTHR) {
        int ln = it & 31;
        int kb = (it >> 5) & 15;
        int rg = it >> 9;
        int g = ln >> 2, tg = ln & 3;
        int r0 = rg * 16 + g, r1 = r0 + 8;
        int c0 = kb * 16 + tg * 2;
        int gr0 = row0 + r0, gr1 = row0 + r1;
        float2 z2 = make_float2(0.f, 0.f);
        float2 v00 = (gr0 < Bn) ? *reinterpret_cast<const float2*>(x + (size_t)gr0 * N_FEAT + c0)     : z2;
        float2 v01 = (gr0 < Bn) ? *reinterpret_cast<const float2*>(x + (size_t)gr0 * N_FEAT + c0 + 8) : z2;
        float2 v10 = (gr1 < Bn) ? *reinterpret_cast<const float2*>(x + (size_t)gr1 * N_FEAT + c0)     : z2;
        float2 v11 = (gr1 < Bn) ? *reinterpret_cast<const float2*>(x + (size_t)gr1 * N_FEAT + c0 + 8) : z2;
        __half2 h00 = __floats2half2_rn(v00.x, v00.y);
        __half2 h10 = __floats2half2_rn(v10.x, v10.y);
        __half2 h01 = __floats2half2_rn(v01.x, v01.y);
        __half2 h11 = __floats2half2_rn(v11.x, v11.y);
        uint4 o;
        o.x = *reinterpret_cast<uint32_t*>(&h00);
        o.y = *reinterpret_cast<uint32_t*>(&h10);
        o.z = *reinterpret_cast<uint32_t*>(&h01);
        o.w = *reinterpret_cast<uint32_t*>(&h11);
        afrag[(rg * 16 + kb) * 32 + ln] = o;
    }
    __syncthreads();

    const int wid = tid >> 5, lane = tid & 31;
    const int rg = wid >> 1, jhalf = wid & 1;
    const int g = lane >> 2, tg = lane & 3;

    float partial0 = 0.f, partial1 = 0.f;

    for (int jt = 0; jt < 4; ++jt) {
        const int kb0 = jt * 4;

        float acc[4][4];
#pragma unroll
        for (int s = 0; s < 4; ++s)
#pragma unroll
            for (int q = 0; q < 4; ++q) acc[s][q] = 0.f;

        const uint4* ap = &afrag[(rg * 16 + kb0) * 32 + lane];
        const uint4* bp = &g_Bf[(((jt * 16 + kb0) * 2 + jhalf) * 2) * 32 + lane];

        // prefetch first k-block
        uint4 a_cur = *ap;
        uint4 b0_cur = bp[0];
        uint4 b1_cur = bp[32];

        for (int kb = kb0; kb < 16; ++kb) {
            uint4 a_nxt, b0_nxt, b1_nxt;
            if (kb + 1 < 16) {
                a_nxt  = ap[32];
                b0_nxt = bp[128];
                b1_nxt = bp[128 + 32];
            }
            uint32_t a[4] = {a_cur.x, a_cur.y, a_cur.z, a_cur.w};
            mma_f16(acc[0], a, b0_cur.x, b0_cur.y);
            mma_f16(acc[1], a, b0_cur.z, b0_cur.w);
            mma_f16(acc[2], a, b1_cur.x, b1_cur.y);
            mma_f16(acc[3], a, b1_cur.z, b1_cur.w);
            a_cur = a_nxt; b0_cur = b0_nxt; b1_cur = b1_nxt;
            ap += 32;
            bp += 128;
        }

        // ---- fused epilogue: partial += (Z + w) .* x over this warp's 32 cols ----
        // acc indexed by LOCAL sub sl; global sub se = jhalf*4 + sl for column numbering.
#pragma unroll
        for (int spair = 0; spair < 2; ++spair) {
            int kbp = jt * 4 + jhalf * 2 + spair;
            uint4 av = afrag[(rg * 16 + kbp) * 32 + lane];
            int sl = spair * 2;
            int se = jhalf * 4 + sl;
            int jbase = jt * 64 + se * 8 + tg * 2;
            float we0 = wls[jbase],     we1 = wls[jbase + 1];
            float wo0 = wls[jbase + 8], wo1 = wls[jbase + 9];
            float2 xe0 = __half22float2(*reinterpret_cast<__half2*>(&av.x));  // row g, even sub
            float2 xe1 = __half22float2(*reinterpret_cast<__half2*>(&av.y));  // row g+8
            float2 xo0 = __half22float2(*reinterpret_cast<__half2*>(&av.z));  // row g, odd sub
            float2 xo1 = __half22float2(*reinterpret_cast<__half2*>(&av.w));  // row g+8
            partial0 += (acc[sl][0] + we0) * xe0.x + (acc[sl][1] + we1) * xe0.y;
            partial1 += (acc[sl][2] + we0) * xe1.x + (acc[sl][3] + we1) * xe1.y;
            partial0 += (acc[sl + 1][0] + wo0) * xo0.x + (acc[sl + 1][1] + wo1) * xo0.y;
            partial1 += (acc[sl + 1][2] + wo0) * xo1.x + (acc[sl + 1][3] + wo1) * xo1.y;
        }
    }

    // reduce over the 4 lanes (tg) sharing each row
    partial0 += __shfl_xor_sync(0xffffffffu, partial0, 1);
    partial0 += __shfl_xor_sync(0xffffffffu, partial0, 2);
    partial1 += __shfl_xor_sync(0xffffffffu, partial1, 1);
    partial1 += __shfl_xor_sync(0xffffffffu, partial1, 2);

    if (tg == 0) {
        atomicAdd(&rowsum[rg * 16 + g],     partial0);
        atomicAdd(&rowsum[rg * 16 + g + 8], partial1);
    }
    __syncthreads();

    if (tid < ROWS) {
        int gr = row0 + tid;
        if (gr < Bn) out[gr] = rowsum[tid] + bl[0];
    }
}

// ---------------------------------------------------------------------------
extern "C" void kernel_launch(void* const* d_in, const int* in_sizes, int n_in,
                              void* d_out, int out_size) {
    const float* x    = (const float*)d_in[0];
    const float* wlin = (const float*)d_in[1];
    const float* blin = (const float*)d_in[2];
    const float* v    = (const float*)d_in[3];
    const int*   fidx = (const int*)d_in[4];
    float* out = (float*)d_out;

    int Bn = in_sizes[0] / N_FEAT;

    ffm_prep<<<128, 128>>>(v, fidx);

    cudaFuncSetAttribute(ffm_main, cudaFuncAttributeMaxDynamicSharedMemorySize, SMEM_TOTAL);
    int grid = (Bn + ROWS - 1) / ROWS;
    ffm_main<<<grid, NTHR, SMEM_TOTAL>>>(x, wlin, blin, out, Bn);
}